// round 15
// baseline (speedup 1.0000x reference)
#include <cuda_runtime.h>
#include <math.h>

#define NT   512        // threads per block
#define GBSZ 16         // batch rows per block
#define HID  128

// ---------------- shared memory layout (float offsets) ----------------
#define OFF_WHH  0                      // 384*128 = 49152 (swizzled float4)
#define OFF_H0   49152                  // 16*128  = 2048  (h buffer 0)
#define OFF_H1   51200                  // 16*128  = 2048  (h buffer 1)
#define OFF_LIFT 53248                  // 16*32   = 512
#define OFF_WHD  53760                  // 19*132  = 2508 -> 2512
#define OFF_WLF  56272                  // 9*32    = 288
#define OFF_BRZ  56560                  // 256: [j]=bihR+bhhR, [128+j]=bihZ+bhhZ
#define OFF_BN   56816                  // 256: [j]=biN, [128+j]=bhN
#define OFF_BHD  57072                  // 19 -> 20
#define OFF_BLF  57092                  // 32
#define OFF_U2Y  57124                  // 20
#define OFF_FEAT 57144                  // 16*10 = 160
#define OFF_TH   57304                  // 16*19 = 304
#define OFF_Y    57608                  // 16*15 = 240
#define OFF_YT   57848                  // 16*15 = 240
#define OFF_DT   58088                  // 16
#define SMEM_FLOATS 58104
#define SMEM_BYTES (SMEM_FLOATS * 4)    // 232416 <= 232448

typedef unsigned long long ull;

// pair barrier: 64 threads = row warp w and D-warp w+8, id = w+1 (1..8)
#define PAIR_BAR(id) asm volatile("bar.sync %0, 64;" :: "r"(id) : "memory")

// packed w_ih: [gate][ph(0..7)][j(0..127)] float4, elems i = 4ph..4ph+3
__device__ float g_wihQ[3 * 8 * 128 * 4];

__global__ void prep_wih_kernel(const float* __restrict__ w_ih) {
    int idx = blockIdx.x * blockDim.x + threadIdx.x;   // over 3*8*128
    if (idx < 3 * 8 * 128) {
        int g  = idx / (8 * 128);
        int r  = idx % (8 * 128);
        int ph = r / 128;
        int j  = r % 128;
        #pragma unroll
        for (int e = 0; e < 4; ++e)
            g_wihQ[idx * 4 + e] = w_ih[(g * 128 + j) * 32 + 4 * ph + e];
    }
}

__device__ __forceinline__ float sigmoid_acc(float x) {
    return 1.0f / (1.0f + __expf(-x));
}
__device__ __forceinline__ float tanh_acc(float x) {
    float ax = fabsf(x);
    float e  = __expf(2.0f * ax);          // inf-safe
    float t  = 1.0f - 2.0f / (e + 1.0f);
    return copysignf(t, x);
}

__device__ __forceinline__ ull ffma2(ull a, ull b, ull c) {
    ull d;
    asm("fma.rn.f32x2 %0, %1, %2, %3;" : "=l"(d) : "l"(a), "l"(b), "l"(c));
    return d;
}
__device__ __forceinline__ float red2(ull v) {
    float lo, hi;
    asm("mov.b64 {%0,%1}, %2;" : "=f"(lo), "=f"(hi) : "l"(v));
    return lo + hi;
}

__global__ __launch_bounds__(NT, 1)
void rnn_chain_kernel(
    const float* __restrict__ y0,       // (B,5)
    const float* __restrict__ u_seq,    // (B,K,4)
    const float* __restrict__ dt_seq,   // (B,K)
    const float* __restrict__ y_seq,    // (B,K,5)
    const float* __restrict__ W_lift,   // (9,32)
    const float* __restrict__ b_lift,   // (32)
    const float* __restrict__ w_hh,     // (384,128)
    const float* __restrict__ b_ih,     // (384)
    const float* __restrict__ b_hh,     // (384)
    const float* __restrict__ W_head,   // (128,19)
    const float* __restrict__ b_head,   // (19)
    const float* __restrict__ u2y,      // (4,5)
    const int*   __restrict__ tfe,      // scalar
    float* __restrict__ out_y,          // (B,K,5)
    float* __restrict__ out_theta,     // (B,K,19)
    int B, int K)
{
    extern __shared__ float sm[];
    const int tid  = threadIdx.x;
    const int lane = tid & 31;
    const int wid  = tid >> 5;            // 0..15
    const int bg   = blockIdx.x * GBSZ;
    const int tf_every = tfe[0];

    // ---------- one-time loads into shared ----------
    {
        // w_hh: swizzled float4 store for conflict-free LDS.128 (q ^ (j&7))
        const float4* src = (const float4*)w_hh;
        float4* w4 = (float4*)(sm + OFF_WHH);
        for (int idx = tid; idx < 384 * 32; idx += NT) {
            int jj = idx >> 5, q = idx & 31;
            w4[(jj << 5) | (q ^ (jj & 7))] = src[idx];
        }
        // W_head transposed: [o][i] pitch 132
        for (int idx = tid; idx < 19 * 128; idx += NT) {
            int o = idx / 128, i = idx % 128;
            sm[OFF_WHD + o * 132 + i] = W_head[i * 19 + o];
        }
        for (int idx = tid; idx < 288; idx += NT) sm[OFF_WLF + idx] = W_lift[idx];
        // combined biases
        for (int idx = tid; idx < 256; idx += NT)
            sm[OFF_BRZ + idx] = b_ih[idx] + b_hh[idx];
        for (int idx = tid; idx < 128; idx += NT) {
            sm[OFF_BN + idx]       = b_ih[256 + idx];
            sm[OFF_BN + 128 + idx] = b_hh[256 + idx];
        }
        if (tid < 19) sm[OFF_BHD + tid] = b_head[tid];
        if (tid < 32) sm[OFF_BLF + tid] = b_lift[tid];
        if (tid < 20) sm[OFF_U2Y + tid] = u2y[tid];
        for (int idx = tid; idx < GBSZ * HID; idx += NT) {
            sm[OFF_H0 + idx] = 0.0f;
            sm[OFF_H1 + idx] = 0.0f;
        }
        for (int idx = tid; idx < GBSZ * 15; idx += NT) {
            int g = idx / 15, i = idx % 15;
            float v = 0.0f;
            if (i < 13) {
                v = 0.01f;
                if (i % 3 == 0) {
                    int p = i / 3;
                    int bgg = bg + g;
                    if (bgg < B) v = 0.01f + y0[bgg * 5 + p];
                }
            }
            sm[OFF_Y  + idx] = v;
            sm[OFF_YT + idx] = 0.0f;
        }
    }
    __syncthreads();

    // B/C mapping: warp-uniform gq, 32 distinct j per warp
    const int gq  = tid >> 7;             // 0..3
    const int g0  = gq * 4;
    const int j   = tid & 127;
    const int sjw = j & 7;

    const float brzR = sm[OFF_BRZ + j];
    const float brzZ = sm[OFF_BRZ + 128 + j];
    const float biN  = sm[OFF_BN + j];
    const float bhN  = sm[OFF_BN + 128 + j];

    // role split: row warps (wid<8) run E/A for rows 2w,2w+1 (half-warp each);
    //             D warps (wid>=8) run the head for the SAME rows 2w,2w+1.
    const bool rw   = (wid < 8);
    const int  w8   = wid & 7;            // pair index 0..7
    const int  pbid = w8 + 1;             // pair barrier id 1..8
    const int  sub  = lane >> 4;          // 0..1
    const int  l    = lane & 15;
    const int  gA   = 2 * w8 + sub;       // row for E/A (row warps)
    const int  bgg  = bg + gA;
    const bool vb   = rw && (bgg < B);

    // ---- D: head for rows 2*w8, 2*w8+1 (executed by D warps) ----
    auto do_D = [&](int kk, const float* hbuf) {
        int o = (lane < 19) ? lane : 18;
        int rowA = 2 * w8, rowB = rowA + 1;
        const ull* hA = (const ull*)(hbuf + rowA * HID);
        const ull* hB = (const ull*)(hbuf + rowB * HID);
        const ulonglong2* wt2 = (const ulonglong2*)(sm + OFF_WHD + o * 132);
        ull a0 = 0ULL, a1 = 0ULL, b0 = 0ULL, b1 = 0ULL;
        #pragma unroll 8
        for (int v = 0; v < 32; ++v) {
            ulonglong2 w = wt2[v];
            ull ha0 = hA[2 * v], ha1 = hA[2 * v + 1];
            ull hb0 = hB[2 * v], hb1 = hB[2 * v + 1];
            a0 = ffma2(ha0, w.x, a0);
            a1 = ffma2(ha1, w.y, a1);
            b0 = ffma2(hb0, w.x, b0);
            b1 = ffma2(hb1, w.y, b1);
        }
        float bh   = sm[OFF_BHD + o];
        float accA = bh + red2(a0) + red2(a1);
        float accB = bh + red2(b0) + red2(b1);
        float thA  = fmaf(1.999f, sigmoid_acc(accA), 0.001f);
        float thB  = fmaf(1.999f, sigmoid_acc(accB), 0.001f);
        if (lane < 19) {
            sm[OFF_TH + rowA * 19 + lane] = thA;
            sm[OFF_TH + rowB * 19 + lane] = thB;
            int ba = bg + rowA, bb = bg + rowB;
            if (ba < B) out_theta[((size_t)ba * K + kk) * 19 + lane] = thA;
            if (bb < B) out_theta[((size_t)bb * K + kk) * 19 + lane] = thB;
        }
    };

    // ---- E: obs jump + RK4 (row warps, half-warp on row gA) ----
    auto do_E = [&](int kk) {
        float dt = sm[OFF_DT + gA];
        if (l < 5) {
            float jp = 0.0f;
            #pragma unroll
            for (int u = 0; u < 4; ++u)
                jp = fmaf(sm[OFF_FEAT + gA * 10 + u], sm[OFF_U2Y + u * 5 + l], jp);
            sm[OFF_Y + gA * 15 + 3 * l] += jp;
        }
        __syncwarp();

        const float* th = sm + OFF_TH + gA * 19;
        int   i  = l;
        bool  act = (i < 13);
        int   ii = act ? i : 13;
        int   im = (ii > 0) ? ii - 1 : 0;
        int   ip = ii + 1;                // <= 14, pads are 0
        float ca = 0.0f, cb = 0.0f, cc = 0.0f;
        if (i == 0)       { cb = -th[0];  cc = th[12]; }
        else if (i == 12) { ca = th[11];  cb = -th[18]; }
        else if (i < 12) {
            if (i & 1) { ca = th[i-1]; cb = -(th[12 + (i >> 1)] + th[i]);
                         cc = (i == 11) ? th[18] : 0.0f; }
            else       { ca = th[i-1]; cb = -th[i]; cc = th[12 + (i >> 1)]; }
        }

        float* yv = sm + OFF_Y  + gA * 15;
        float* yt = sm + OFF_YT + gA * 15;
        float y0v = yv[ii];
        float hdt = 0.5f * dt;

        float ym = yv[im], yc = yv[ii], yp = yv[ip];
        float d1 = ca * ym + cb * yc + cc * yp;
        float ks = d1;
        __syncwarp();
        if (act) yt[i] = fmaf(hdt, d1, y0v);
        __syncwarp();
        ym = yt[im]; yc = yt[ii]; yp = yt[ip];
        float d2 = ca * ym + cb * yc + cc * yp;
        ks = fmaf(2.0f, d2, ks);
        __syncwarp();
        if (act) yt[i] = fmaf(hdt, d2, y0v);
        __syncwarp();
        ym = yt[im]; yc = yt[ii]; yp = yt[ip];
        float d3 = ca * ym + cb * yc + cc * yp;
        ks = fmaf(2.0f, d3, ks);
        __syncwarp();
        if (act) yt[i] = fmaf(dt, d3, y0v);
        __syncwarp();
        ym = yt[im]; yc = yt[ii]; yp = yt[ip];
        float d4 = ca * ym + cb * yc + cc * yp;
        ks += d4;

        float ynew = fmaf(dt * (1.0f / 6.0f), ks, y0v);
        ynew = fmaxf(ynew, 0.0f);
        __syncwarp();
        if (act) yv[i] = ynew;
        __syncwarp();
        if (l < 5 && vb)
            out_y[((size_t)bgg * K + kk) * 5 + l] = yv[3 * l];
    };

    // prefetch registers for step-0 inputs (slot by l; row warps only)
    float pf = 0.0f;
    if (vb) {
        if (l < 4)       pf = u_seq[((size_t)bgg * K) * 4 + l];
        else if (l == 9) pf = dt_seq[(size_t)bgg * K];
    }

    for (int k = 0; k < K; ++k) {
        const float* hc  = sm + ((k & 1) ? OFF_H1 : OFF_H0);   // h(k-1)
        float*       hnx = sm + ((k & 1) ? OFF_H0 : OFF_H1);   // h(k)

        // ===== D warps: head(k-1) immediately (h(k-1) ready at bar2), then
        //       arrive at the pair barrier so the row warp can run E(k-1).
        if (!rw && k > 0) {
            do_D(k - 1, hc);
            PAIR_BAR(pbid);
        }

        // ===== gh(k) FIRST HALF (q=0..15): overlaps D / fills phase 1 ========
        ull aR2[4], aZ2[4], aNx2[4], aNh2[4];
        #pragma unroll
        for (int t = 0; t < 4; ++t) { aR2[t] = 0ULL; aZ2[t] = 0ULL; aNx2[t] = 0ULL; aNh2[t] = 0ULL; }
        {
            const ulonglong2* w2 = (const ulonglong2*)(sm + OFF_WHH);
            const ulonglong2* h2 = (const ulonglong2*)hc;
            #pragma unroll 4
            for (int q = 0; q < 16; ++q) {
                int qs = q ^ sjw;
                ulonglong2 wr = w2[((j      ) << 5) | qs];
                ulonglong2 wz = w2[((j + 128) << 5) | qs];
                ulonglong2 wn = w2[((j + 256) << 5) | qs];
                #pragma unroll
                for (int t = 0; t < 4; ++t) {
                    ulonglong2 hv = h2[(g0 + t) * 32 + q];
                    aR2[t]  = ffma2(hv.x, wr.x, aR2[t]);
                    aR2[t]  = ffma2(hv.y, wr.y, aR2[t]);
                    aZ2[t]  = ffma2(hv.x, wz.x, aZ2[t]);
                    aZ2[t]  = ffma2(hv.y, wz.y, aZ2[t]);
                    aNh2[t] = ffma2(hv.x, wn.x, aNh2[t]);
                    aNh2[t] = ffma2(hv.y, wn.y, aNh2[t]);
                }
            }
        }

        // ===== row warps: wait for TH(k-1), then E(k-1), then A(k) ==========
        if (rw) {
            if (k > 0) {
                PAIR_BAR(pbid);
                do_E(k - 1);
            }
            // ---- A: features + lift (half-warp on row gA) ----
            bool tf = (k > 0) && (k % tf_every == 0);
            if (l < 4) {
                sm[OFF_FEAT + gA * 10 + l] = vb ? pf : 0.0f;
            } else if (l < 9) {
                float yp = tf ? (vb ? pf : 0.0f) : sm[OFF_Y + gA * 15 + 3 * (l - 4)];
                sm[OFF_FEAT + gA * 10 + l] = yp;
            } else if (l == 9) {
                sm[OFF_DT + gA] = vb ? pf : 0.01f;
            }
            __syncwarp();
            float f[9];
            #pragma unroll
            for (int i = 0; i < 9; ++i) f[i] = sm[OFF_FEAT + gA * 10 + i];
            #pragma unroll
            for (int cc = 0; cc < 2; ++cc) {
                int c = l + cc * 16;
                float acc = sm[OFF_BLF + c];
                #pragma unroll
                for (int i = 0; i < 9; ++i)
                    acc = fmaf(f[i], sm[OFF_WLF + i * 32 + c], acc);
                float s = sigmoid_acc(acc);
                sm[OFF_LIFT + gA * 32 + c] = acc * s;   // silu
            }
        }

        // ================= prefetch k+1 globals ===============================
        float pfn = 0.0f;
        {
            int kn = k + 1;
            if (kn < K && vb) {
                bool tfn = (kn % tf_every) == 0;
                if (l < 4)       pfn = u_seq[((size_t)bgg * K + kn) * 4 + l];
                else if (l < 9)  { if (tfn) pfn = y_seq[((size_t)bgg * K + kn - 1) * 5 + (l - 4)]; }
                else if (l == 9) pfn = dt_seq[(size_t)bgg * K + kn];
            }
        }
        __syncthreads();   // bar1: lift(k) ready block-wide

        // ================= gx(k): w_ih from L2 (loads issue early) ============
        {
            const ulonglong2* wQ  = (const ulonglong2*)g_wihQ;
            const ulonglong2* lf4 = (const ulonglong2*)(sm + OFF_LIFT);
            #pragma unroll 2
            for (int ph = 0; ph < 8; ++ph) {
                ulonglong2 wr = wQ[(0 * 8 + ph) * 128 + j];
                ulonglong2 wz = wQ[(1 * 8 + ph) * 128 + j];
                ulonglong2 wn = wQ[(2 * 8 + ph) * 128 + j];
                #pragma unroll
                for (int t = 0; t < 4; ++t) {
                    ulonglong2 lf = lf4[(g0 + t) * 8 + ph];
                    aR2[t]  = ffma2(lf.x, wr.x, aR2[t]);
                    aR2[t]  = ffma2(lf.y, wr.y, aR2[t]);
                    aZ2[t]  = ffma2(lf.x, wz.x, aZ2[t]);
                    aZ2[t]  = ffma2(lf.y, wz.y, aZ2[t]);
                    aNx2[t] = ffma2(lf.x, wn.x, aNx2[t]);
                    aNx2[t] = ffma2(lf.y, wn.y, aNx2[t]);
                }
            }
        }

        // ================= gh(k) SECOND HALF (q=16..31): fills phase 2 ========
        {
            const ulonglong2* w2 = (const ulonglong2*)(sm + OFF_WHH);
            const ulonglong2* h2 = (const ulonglong2*)hc;
            #pragma unroll 4
            for (int q = 16; q < 32; ++q) {
                int qs = q ^ sjw;
                ulonglong2 wr = w2[((j      ) << 5) | qs];
                ulonglong2 wz = w2[((j + 128) << 5) | qs];
                ulonglong2 wn = w2[((j + 256) << 5) | qs];
                #pragma unroll
                for (int t = 0; t < 4; ++t) {
                    ulonglong2 hv = h2[(g0 + t) * 32 + q];
                    aR2[t]  = ffma2(hv.x, wr.x, aR2[t]);
                    aR2[t]  = ffma2(hv.y, wr.y, aR2[t]);
                    aZ2[t]  = ffma2(hv.x, wz.x, aZ2[t]);
                    aZ2[t]  = ffma2(hv.y, wz.y, aZ2[t]);
                    aNh2[t] = ffma2(hv.x, wn.x, aNh2[t]);
                    aNh2[t] = ffma2(hv.y, wn.y, aNh2[t]);
                }
            }
        }

        // ================= C: gates + h update (write to OTHER buffer) ========
        #pragma unroll
        for (int t = 0; t < 4; ++t) {
            float r  = sigmoid_acc(red2(aR2[t]) + brzR);
            float z  = sigmoid_acc(red2(aZ2[t]) + brzZ);
            float nx = red2(aNx2[t]) + biN;
            float nh = red2(aNh2[t]) + bhN;
            float n  = tanh_acc(fmaf(r, nh, nx));
            float ho = hc[(g0 + t) * HID + j];
            hnx[(g0 + t) * HID + j] = fmaf(z, ho - n, n);   // (1-z)n + z h
        }
        __syncthreads();   // bar2: h(k) complete & visible

        pf = pfn;
    }

    // epilogue: D/E for the final step (h(K-1) is in the last written buffer)
    {
        const float* hl = sm + (((K - 1) & 1) ? OFF_H0 : OFF_H1);
        if (!rw) {
            do_D(K - 1, hl);
            PAIR_BAR(pbid);
        } else {
            PAIR_BAR(pbid);
            do_E(K - 1);
        }
    }
}

extern "C" void kernel_launch(void* const* d_in, const int* in_sizes, int n_in,
                              void* d_out, int out_size) {
    const float* y0     = (const float*)d_in[0];
    const float* u_seq  = (const float*)d_in[1];
    const float* dt_seq = (const float*)d_in[2];
    const float* y_seq  = (const float*)d_in[3];
    const float* W_lift = (const float*)d_in[4];
    const float* b_lift = (const float*)d_in[5];
    const float* w_ih   = (const float*)d_in[6];
    const float* w_hh   = (const float*)d_in[7];
    const float* b_ih   = (const float*)d_in[8];
    const float* b_hh   = (const float*)d_in[9];
    const float* W_head = (const float*)d_in[10];
    const float* b_head = (const float*)d_in[11];
    const float* u2y    = (const float*)d_in[12];
    const int*   tfe    = (const int*)d_in[13];

    int B = in_sizes[0] / 5;
    int K = in_sizes[1] / (B * 4);

    float* out_y     = (float*)d_out;
    float* out_theta = (float*)d_out + (size_t)B * K * 5;

    prep_wih_kernel<<<(3 * 8 * 128 + 255) / 256, 256>>>(w_ih);

    cudaFuncSetAttribute(rnn_chain_kernel,
                         cudaFuncAttributeMaxDynamicSharedMemorySize, SMEM_BYTES);

    int grid = (B + GBSZ - 1) / GBSZ;
    rnn_chain_kernel<<<grid, NT, SMEM_BYTES>>>(
        y0, u_seq, dt_seq, y_seq, W_lift, b_lift, w_hh, b_ih, b_hh,
        W_head, b_head, u2y, tfe, out_y, out_theta, B, K);
}

// round 16
// speedup vs baseline: 1.0789x; 1.0789x over previous
#include <cuda_runtime.h>
#include <math.h>

#define NT   512        // threads per block
#define GBSZ 16         // batch rows per block
#define HID  128

// ---------------- shared memory layout (float offsets) ----------------
#define OFF_WHH  0                      // 384*128 = 49152 (swizzled float4)
#define OFF_H0   49152                  // 16*128  = 2048  (h buffer 0)
#define OFF_H1   51200                  // 16*128  = 2048  (h buffer 1)
#define OFF_LIFT 53248                  // 16*32   = 512
#define OFF_WHD  53760                  // 19*132  = 2508 -> 2512
#define OFF_WLF  56272                  // 9*32    = 288
#define OFF_BRZ  56560                  // 256: [j]=bihR+bhhR, [128+j]=bihZ+bhhZ
#define OFF_BN   56816                  // 256: [j]=biN, [128+j]=bhN
#define OFF_BHD  57072                  // 19 -> 20
#define OFF_BLF  57092                  // 32
#define OFF_U2Y  57124                  // 20
#define OFF_FEAT 57144                  // 16*10 = 160
#define OFF_TH   57304                  // 16*19 = 304
#define OFF_Y    57608                  // 16*15 = 240
#define OFF_YT   57848                  // 16*15 = 240
#define OFF_DT   58088                  // 16
#define SMEM_FLOATS 58104
#define SMEM_BYTES (SMEM_FLOATS * 4)    // 232416 <= 232448

typedef unsigned long long ull;

// pair barrier: 64 threads = row warp w and D-warp w+8, id = w+1 (1..8)
#define PAIR_BAR(id) asm volatile("bar.sync %0, 64;" :: "r"(id) : "memory")

// packed w_ih: [gate][ph(0..7)][j(0..127)] float4, elems i = 4ph..4ph+3
__device__ float g_wihQ[3 * 8 * 128 * 4];

__global__ void prep_wih_kernel(const float* __restrict__ w_ih) {
    int idx = blockIdx.x * blockDim.x + threadIdx.x;   // over 3*8*128
    if (idx < 3 * 8 * 128) {
        int g  = idx / (8 * 128);
        int r  = idx % (8 * 128);
        int ph = r / 128;
        int j  = r % 128;
        #pragma unroll
        for (int e = 0; e < 4; ++e)
            g_wihQ[idx * 4 + e] = w_ih[(g * 128 + j) * 32 + 4 * ph + e];
    }
}

__device__ __forceinline__ float sigmoid_acc(float x) {
    return __fdividef(1.0f, 1.0f + __expf(-x));
}
__device__ __forceinline__ float tanh_acc(float x) {
    float ax = fabsf(x);
    float e  = __expf(2.0f * ax);          // inf-safe (e=inf -> t=1)
    float t  = 1.0f - __fdividef(2.0f, e + 1.0f);
    return copysignf(t, x);
}

__device__ __forceinline__ ull ffma2(ull a, ull b, ull c) {
    ull d;
    asm("fma.rn.f32x2 %0, %1, %2, %3;" : "=l"(d) : "l"(a), "l"(b), "l"(c));
    return d;
}
__device__ __forceinline__ float red2(ull v) {
    float lo, hi;
    asm("mov.b64 {%0,%1}, %2;" : "=f"(lo), "=f"(hi) : "l"(v));
    return lo + hi;
}

__global__ __launch_bounds__(NT, 1)
void rnn_chain_kernel(
    const float* __restrict__ y0,       // (B,5)
    const float* __restrict__ u_seq,    // (B,K,4)
    const float* __restrict__ dt_seq,   // (B,K)
    const float* __restrict__ y_seq,    // (B,K,5)
    const float* __restrict__ W_lift,   // (9,32)
    const float* __restrict__ b_lift,   // (32)
    const float* __restrict__ w_hh,     // (384,128)
    const float* __restrict__ b_ih,     // (384)
    const float* __restrict__ b_hh,     // (384)
    const float* __restrict__ W_head,   // (128,19)
    const float* __restrict__ b_head,   // (19)
    const float* __restrict__ u2y,      // (4,5)
    const int*   __restrict__ tfe,      // scalar
    float* __restrict__ out_y,          // (B,K,5)
    float* __restrict__ out_theta,     // (B,K,19)
    int B, int K)
{
    extern __shared__ float sm[];
    const int tid  = threadIdx.x;
    const int lane = tid & 31;
    const int wid  = tid >> 5;            // 0..15
    const int bg   = blockIdx.x * GBSZ;
    const int tf_every = tfe[0];

    // ---------- one-time loads into shared ----------
    {
        // w_hh: swizzled float4 store for conflict-free LDS.128 (q ^ (j&7))
        const float4* src = (const float4*)w_hh;
        float4* w4 = (float4*)(sm + OFF_WHH);
        for (int idx = tid; idx < 384 * 32; idx += NT) {
            int jj = idx >> 5, q = idx & 31;
            w4[(jj << 5) | (q ^ (jj & 7))] = src[idx];
        }
        // W_head transposed: [o][i] pitch 132
        for (int idx = tid; idx < 19 * 128; idx += NT) {
            int o = idx / 128, i = idx % 128;
            sm[OFF_WHD + o * 132 + i] = W_head[i * 19 + o];
        }
        for (int idx = tid; idx < 288; idx += NT) sm[OFF_WLF + idx] = W_lift[idx];
        // combined biases
        for (int idx = tid; idx < 256; idx += NT)
            sm[OFF_BRZ + idx] = b_ih[idx] + b_hh[idx];
        for (int idx = tid; idx < 128; idx += NT) {
            sm[OFF_BN + idx]       = b_ih[256 + idx];
            sm[OFF_BN + 128 + idx] = b_hh[256 + idx];
        }
        if (tid < 19) sm[OFF_BHD + tid] = b_head[tid];
        if (tid < 32) sm[OFF_BLF + tid] = b_lift[tid];
        if (tid < 20) sm[OFF_U2Y + tid] = u2y[tid];
        for (int idx = tid; idx < GBSZ * HID; idx += NT) {
            sm[OFF_H0 + idx] = 0.0f;
            sm[OFF_H1 + idx] = 0.0f;
        }
        for (int idx = tid; idx < GBSZ * 15; idx += NT) {
            int g = idx / 15, i = idx % 15;
            float v = 0.0f;
            if (i < 13) {
                v = 0.01f;
                if (i % 3 == 0) {
                    int p = i / 3;
                    int bgg = bg + g;
                    if (bgg < B) v = 0.01f + y0[bgg * 5 + p];
                }
            }
            sm[OFF_Y  + idx] = v;
            sm[OFF_YT + idx] = 0.0f;
        }
    }
    __syncthreads();

    // B/C mapping: warp-uniform gq, 32 distinct j per warp
    const int gq  = tid >> 7;             // 0..3
    const int g0  = gq * 4;
    const int j   = tid & 127;
    const int sjw = j & 7;

    const float brzR = sm[OFF_BRZ + j];
    const float brzZ = sm[OFF_BRZ + 128 + j];
    const float biN  = sm[OFF_BN + j];
    const float bhN  = sm[OFF_BN + 128 + j];

    // role split: row warps (wid<8) run E/A for rows 2w,2w+1 (half-warp each);
    //             D warps (wid>=8) run the head for the SAME rows 2w,2w+1.
    const bool rw   = (wid < 8);
    const int  w8   = wid & 7;            // pair index 0..7
    const int  pbid = w8 + 1;             // pair barrier id 1..8
    const int  sub  = lane >> 4;          // 0..1
    const int  l    = lane & 15;
    const int  gA   = 2 * w8 + sub;       // row for E/A (row warps)
    const int  bgg  = bg + gA;
    const bool vb   = rw && (bgg < B);

    // ---- D: head for rows 2*w8, 2*w8+1 (executed by D warps) ----
    auto do_D = [&](int kk, const float* hbuf) {
        int o = (lane < 19) ? lane : 18;
        int rowA = 2 * w8, rowB = rowA + 1;
        const ull* hA = (const ull*)(hbuf + rowA * HID);
        const ull* hB = (const ull*)(hbuf + rowB * HID);
        const ulonglong2* wt2 = (const ulonglong2*)(sm + OFF_WHD + o * 132);
        ull a0 = 0ULL, a1 = 0ULL, b0 = 0ULL, b1 = 0ULL;
        #pragma unroll 8
        for (int v = 0; v < 32; ++v) {
            ulonglong2 w = wt2[v];
            ull ha0 = hA[2 * v], ha1 = hA[2 * v + 1];
            ull hb0 = hB[2 * v], hb1 = hB[2 * v + 1];
            a0 = ffma2(ha0, w.x, a0);
            a1 = ffma2(ha1, w.y, a1);
            b0 = ffma2(hb0, w.x, b0);
            b1 = ffma2(hb1, w.y, b1);
        }
        float bh   = sm[OFF_BHD + o];
        float accA = bh + red2(a0) + red2(a1);
        float accB = bh + red2(b0) + red2(b1);
        float thA  = fmaf(1.999f, sigmoid_acc(accA), 0.001f);
        float thB  = fmaf(1.999f, sigmoid_acc(accB), 0.001f);
        if (lane < 19) {
            sm[OFF_TH + rowA * 19 + lane] = thA;
            sm[OFF_TH + rowB * 19 + lane] = thB;
            int ba = bg + rowA, bb = bg + rowB;
            if (ba < B) out_theta[((size_t)ba * K + kk) * 19 + lane] = thA;
            if (bb < B) out_theta[((size_t)bb * K + kk) * 19 + lane] = thB;
        }
    };

    // ---- E: obs jump + RK4 (row warps, half-warp on row gA) ----
    auto do_E = [&](int kk) {
        float dt = sm[OFF_DT + gA];
        if (l < 5) {
            float jp = 0.0f;
            #pragma unroll
            for (int u = 0; u < 4; ++u)
                jp = fmaf(sm[OFF_FEAT + gA * 10 + u], sm[OFF_U2Y + u * 5 + l], jp);
            sm[OFF_Y + gA * 15 + 3 * l] += jp;
        }
        __syncwarp();

        const float* th = sm + OFF_TH + gA * 19;
        int   i  = l;
        bool  act = (i < 13);
        int   ii = act ? i : 13;
        int   im = (ii > 0) ? ii - 1 : 0;
        int   ip = ii + 1;                // <= 14, pads are 0
        float ca = 0.0f, cb = 0.0f, cc = 0.0f;
        if (i == 0)       { cb = -th[0];  cc = th[12]; }
        else if (i == 12) { ca = th[11];  cb = -th[18]; }
        else if (i < 12) {
            if (i & 1) { ca = th[i-1]; cb = -(th[12 + (i >> 1)] + th[i]);
                         cc = (i == 11) ? th[18] : 0.0f; }
            else       { ca = th[i-1]; cb = -th[i]; cc = th[12 + (i >> 1)]; }
        }

        float* yv = sm + OFF_Y  + gA * 15;
        float* yt = sm + OFF_YT + gA * 15;
        float y0v = yv[ii];
        float hdt = 0.5f * dt;

        float ym = yv[im], yc = yv[ii], yp = yv[ip];
        float d1 = ca * ym + cb * yc + cc * yp;
        float ks = d1;
        __syncwarp();
        if (act) yt[i] = fmaf(hdt, d1, y0v);
        __syncwarp();
        ym = yt[im]; yc = yt[ii]; yp = yt[ip];
        float d2 = ca * ym + cb * yc + cc * yp;
        ks = fmaf(2.0f, d2, ks);
        __syncwarp();
        if (act) yt[i] = fmaf(hdt, d2, y0v);
        __syncwarp();
        ym = yt[im]; yc = yt[ii]; yp = yt[ip];
        float d3 = ca * ym + cb * yc + cc * yp;
        ks = fmaf(2.0f, d3, ks);
        __syncwarp();
        if (act) yt[i] = fmaf(dt, d3, y0v);
        __syncwarp();
        ym = yt[im]; yc = yt[ii]; yp = yt[ip];
        float d4 = ca * ym + cb * yc + cc * yp;
        ks += d4;

        float ynew = fmaf(dt * (1.0f / 6.0f), ks, y0v);
        ynew = fmaxf(ynew, 0.0f);
        __syncwarp();
        if (act) yv[i] = ynew;
        __syncwarp();
        if (l < 5 && vb)
            out_y[((size_t)bgg * K + kk) * 5 + l] = yv[3 * l];
    };

    // prefetch registers for step-0 inputs (slot by l; row warps only)
    float pf = 0.0f;
    if (vb) {
        if (l < 4)       pf = u_seq[((size_t)bgg * K) * 4 + l];
        else if (l == 9) pf = dt_seq[(size_t)bgg * K];
    }

    for (int k = 0; k < K; ++k) {
        const float* hc  = sm + ((k & 1) ? OFF_H1 : OFF_H0);   // h(k-1)
        float*       hnx = sm + ((k & 1) ? OFF_H0 : OFF_H1);   // h(k)

        // ===== D warps: head(k-1) immediately (h(k-1) ready at bar2), then
        //       arrive at the pair barrier so the row warp can run E(k-1).
        if (!rw && k > 0) {
            do_D(k - 1, hc);
            PAIR_BAR(pbid);
        }

        // ===== gh(k): all warps (row warps overlap this with D on D-warps) ===
        ull aR2[4], aZ2[4], aNx2[4], aNh2[4];
        #pragma unroll
        for (int t = 0; t < 4; ++t) { aR2[t] = 0ULL; aZ2[t] = 0ULL; aNx2[t] = 0ULL; aNh2[t] = 0ULL; }
        {
            const ulonglong2* w2 = (const ulonglong2*)(sm + OFF_WHH);
            const ulonglong2* h2 = (const ulonglong2*)hc;
            #pragma unroll 4
            for (int q = 0; q < 32; ++q) {
                int qs = q ^ sjw;
                ulonglong2 wr = w2[((j      ) << 5) | qs];
                ulonglong2 wz = w2[((j + 128) << 5) | qs];
                ulonglong2 wn = w2[((j + 256) << 5) | qs];
                #pragma unroll
                for (int t = 0; t < 4; ++t) {
                    ulonglong2 hv = h2[(g0 + t) * 32 + q];
                    aR2[t]  = ffma2(hv.x, wr.x, aR2[t]);
                    aR2[t]  = ffma2(hv.y, wr.y, aR2[t]);
                    aZ2[t]  = ffma2(hv.x, wz.x, aZ2[t]);
                    aZ2[t]  = ffma2(hv.y, wz.y, aZ2[t]);
                    aNh2[t] = ffma2(hv.x, wn.x, aNh2[t]);
                    aNh2[t] = ffma2(hv.y, wn.y, aNh2[t]);
                }
            }
        }

        // ===== row warps: wait for TH(k-1), then E(k-1), then A(k) ==========
        if (rw) {
            if (k > 0) {
                PAIR_BAR(pbid);
                do_E(k - 1);
            }
            // ---- A: features + lift (half-warp on row gA) ----
            bool tf = (k > 0) && (k % tf_every == 0);
            if (l < 4) {
                sm[OFF_FEAT + gA * 10 + l] = vb ? pf : 0.0f;
            } else if (l < 9) {
                float yp = tf ? (vb ? pf : 0.0f) : sm[OFF_Y + gA * 15 + 3 * (l - 4)];
                sm[OFF_FEAT + gA * 10 + l] = yp;
            } else if (l == 9) {
                sm[OFF_DT + gA] = vb ? pf : 0.01f;
            }
            __syncwarp();
            float f[9];
            #pragma unroll
            for (int i = 0; i < 9; ++i) f[i] = sm[OFF_FEAT + gA * 10 + i];
            #pragma unroll
            for (int cc = 0; cc < 2; ++cc) {
                int c = l + cc * 16;
                float acc = sm[OFF_BLF + c];
                #pragma unroll
                for (int i = 0; i < 9; ++i)
                    acc = fmaf(f[i], sm[OFF_WLF + i * 32 + c], acc);
                float s = sigmoid_acc(acc);
                sm[OFF_LIFT + gA * 32 + c] = acc * s;   // silu
            }
        }

        // ================= prefetch k+1 globals ===============================
        float pfn = 0.0f;
        {
            int kn = k + 1;
            if (kn < K && vb) {
                bool tfn = (kn % tf_every) == 0;
                if (l < 4)       pfn = u_seq[((size_t)bgg * K + kn) * 4 + l];
                else if (l < 9)  { if (tfn) pfn = y_seq[((size_t)bgg * K + kn - 1) * 5 + (l - 4)]; }
                else if (l == 9) pfn = dt_seq[(size_t)bgg * K + kn];
            }
        }
        __syncthreads();   // bar1: lift(k) ready block-wide

        // ================= gx(k): w_ih from L2, lifted broadcasts =============
        {
            const ulonglong2* wQ  = (const ulonglong2*)g_wihQ;
            const ulonglong2* lf4 = (const ulonglong2*)(sm + OFF_LIFT);
            #pragma unroll 2
            for (int ph = 0; ph < 8; ++ph) {
                ulonglong2 wr = wQ[(0 * 8 + ph) * 128 + j];
                ulonglong2 wz = wQ[(1 * 8 + ph) * 128 + j];
                ulonglong2 wn = wQ[(2 * 8 + ph) * 128 + j];
                #pragma unroll
                for (int t = 0; t < 4; ++t) {
                    ulonglong2 lf = lf4[(g0 + t) * 8 + ph];
                    aR2[t]  = ffma2(lf.x, wr.x, aR2[t]);
                    aR2[t]  = ffma2(lf.y, wr.y, aR2[t]);
                    aZ2[t]  = ffma2(lf.x, wz.x, aZ2[t]);
                    aZ2[t]  = ffma2(lf.y, wz.y, aZ2[t]);
                    aNx2[t] = ffma2(lf.x, wn.x, aNx2[t]);
                    aNx2[t] = ffma2(lf.y, wn.y, aNx2[t]);
                }
            }
        }
        // ================= C: gates + h update (write to OTHER buffer) ========
        #pragma unroll
        for (int t = 0; t < 4; ++t) {
            float r  = sigmoid_acc(red2(aR2[t]) + brzR);
            float z  = sigmoid_acc(red2(aZ2[t]) + brzZ);
            float nx = red2(aNx2[t]) + biN;
            float nh = red2(aNh2[t]) + bhN;
            float n  = tanh_acc(fmaf(r, nh, nx));
            float ho = hc[(g0 + t) * HID + j];
            hnx[(g0 + t) * HID + j] = fmaf(z, ho - n, n);   // (1-z)n + z h
        }
        __syncthreads();   // bar2: h(k) complete & visible

        pf = pfn;
    }

    // epilogue: D/E for the final step (h(K-1) is in the last written buffer)
    {
        const float* hl = sm + (((K - 1) & 1) ? OFF_H0 : OFF_H1);
        if (!rw) {
            do_D(K - 1, hl);
            PAIR_BAR(pbid);
        } else {
            PAIR_BAR(pbid);
            do_E(K - 1);
        }
    }
}

extern "C" void kernel_launch(void* const* d_in, const int* in_sizes, int n_in,
                              void* d_out, int out_size) {
    const float* y0     = (const float*)d_in[0];
    const float* u_seq  = (const float*)d_in[1];
    const float* dt_seq = (const float*)d_in[2];
    const float* y_seq  = (const float*)d_in[3];
    const float* W_lift = (const float*)d_in[4];
    const float* b_lift = (const float*)d_in[5];
    const float* w_ih   = (const float*)d_in[6];
    const float* w_hh   = (const float*)d_in[7];
    const float* b_ih   = (const float*)d_in[8];
    const float* b_hh   = (const float*)d_in[9];
    const float* W_head = (const float*)d_in[10];
    const float* b_head = (const float*)d_in[11];
    const float* u2y    = (const float*)d_in[12];
    const int*   tfe    = (const int*)d_in[13];

    int B = in_sizes[0] / 5;
    int K = in_sizes[1] / (B * 4);

    float* out_y     = (float*)d_out;
    float* out_theta = (float*)d_out + (size_t)B * K * 5;

    prep_wih_kernel<<<(3 * 8 * 128 + 255) / 256, 256>>>(w_ih);

    cudaFuncSetAttribute(rnn_chain_kernel,
                         cudaFuncAttributeMaxDynamicSharedMemorySize, SMEM_BYTES);

    int grid = (B + GBSZ - 1) / GBSZ;
    rnn_chain_kernel<<<grid, NT, SMEM_BYTES>>>(
        y0, u_seq, dt_seq, y_seq, W_lift, b_lift, w_hh, b_ih, b_hh,
        W_head, b_head, u2y, tfe, out_y, out_theta, B, K);
}